// round 1
// baseline (speedup 1.0000x reference)
#include <cuda_runtime.h>
#include <cuda_bf16.h>

// Problem constants (fixed by the reference: B=16,S=16 -> BS=256)
#define L_TOK   128          // tokens per sentence
#define NARG    8            // A
#define NTOK    8            // T
#define EMB_D   768          // D
#define DC      256          // D-chunk per CTA
#define NCHUNK  (EMB_D / DC) // 3
#define NP      24           // 3 arg-sets * NARG
#define BDIM    256

// Shared memory layout
struct SmemLayout {
    float tile[L_TOK * DC];      // 131072 B  embedding tile [l][dc]
    int   s_ids[L_TOK];          // sentence ids
    float s_m[L_TOK];            // attention mask (as float)
    int   s_arg[NP * NTOK];      // arg ids, [p][t]
    int   s_list[NP * L_TOK];    // packed (l | w<<8) nonzero entries per p
    int   s_cnt[NP];             // nonzero-entry count per p
    int   s_tot[NP];             // total matched-token count per p
    float s_inv[NP];             // 1/max(tot,1), or 0 if tot==0
    float s_minv;                // 1/max(sum(mask),1)
};

__global__ void __launch_bounds__(BDIM, 1)
slmuse_fused_kernel(const int*   __restrict__ sent_ids,
                    const int*   __restrict__ att_mask,
                    const int*   __restrict__ pred_ids,
                    const int*   __restrict__ arg0_ids,
                    const int*   __restrict__ arg1_ids,
                    const float* __restrict__ emb,
                    float*       __restrict__ out,     // concatenated tuple
                    int BS)                            // B*S = 256
{
    extern __shared__ char smem_raw[];
    SmemLayout* sm = reinterpret_cast<SmemLayout*>(smem_raw);

    const int tid   = threadIdx.x;
    const int bs    = blockIdx.x / NCHUNK;
    const int chunk = blockIdx.x % NCHUNK;

    // Output section base pointers (tuple concatenated in order)
    float* out_mean = out;                                      // [BS, D]
    float* out_sets = out + (size_t)BS * EMB_D;                 // 3 x [BS, A, D]
    const size_t set_stride = (size_t)BS * NARG * EMB_D;

    // ---- Phase 1: load ids / mask / arg ids into smem ----
    if (tid < L_TOK) {
        sm->s_ids[tid] = sent_ids[(size_t)bs * L_TOK + tid];
        sm->s_m[tid]   = (float)att_mask[(size_t)bs * L_TOK + tid];
    }
    if (tid < NP * NTOK) {                 // 192 threads
        int p = tid / NTOK, t = tid % NTOK;
        int set = p / NARG, a = p % NARG;
        const int* src = (set == 0) ? pred_ids : (set == 1) ? arg0_ids : arg1_ids;
        sm->s_arg[tid] = src[((size_t)bs * NARG + a) * NTOK + t];
    }
    if (tid < NP) { sm->s_cnt[tid] = 0; sm->s_tot[tid] = 0; }
    __syncthreads();

    // ---- Phase 2: build compact nonzero weight lists (3072 tiny tasks) ----
    for (int task = tid; task < NP * L_TOK; task += BDIM) {
        int p = task >> 7;          // /128
        int l = task & (L_TOK - 1);
        int sid = sm->s_ids[l];
        int w = 0;
        #pragma unroll
        for (int t = 0; t < NTOK; t++) {
            int aid = sm->s_arg[p * NTOK + t];
            w += (aid != 0 && aid == sid) ? 1 : 0;
        }
        if (w) {
            int pos = atomicAdd(&sm->s_cnt[p], 1);
            sm->s_list[p * L_TOK + pos] = l | (w << 8);
            atomicAdd(&sm->s_tot[p], w);
        }
    }
    __syncthreads();

    if (tid == 0) {
        float ms = 0.f;
        #pragma unroll 8
        for (int l = 0; l < L_TOK; l++) ms += sm->s_m[l];
        sm->s_minv = 1.f / fmaxf(ms, 1.f);
    }
    if (tid < NP) {
        int tot = sm->s_tot[tid];
        sm->s_inv[tid] = (tot > 0) ? (1.f / (float)tot) : 0.f;  // 0 => where(counts>0,...,0)
    }

    // ---- Phase 3: load the 128 x 256 fp32 embedding tile (float4, coalesced) ----
    {
        const size_t row_base = (size_t)bs * L_TOK * EMB_D + (size_t)chunk * DC;
        // L_TOK rows * (DC/4)=64 float4 per row = 8192 slots; 32 per thread
        #pragma unroll 4
        for (int idx = tid; idx < L_TOK * (DC / 4); idx += BDIM) {
            int l  = idx >> 6;          // /64
            int c4 = idx & 63;
            float4 v = *reinterpret_cast<const float4*>(
                emb + row_base + (size_t)l * EMB_D + (size_t)c4 * 4);
            *reinterpret_cast<float4*>(&sm->tile[l * DC + c4 * 4]) = v;
        }
    }
    __syncthreads();

    // ---- Phase 4: compute. Each thread owns one column d = tid of the chunk. ----
    const int dcol = tid;

    // Mean pool: dense over all 128 tokens, 4-way ILP
    {
        float a0 = 0.f, a1 = 0.f, a2 = 0.f, a3 = 0.f;
        #pragma unroll 8
        for (int l = 0; l < L_TOK; l += 4) {
            a0 += sm->s_m[l + 0] * sm->tile[(l + 0) * DC + dcol];
            a1 += sm->s_m[l + 1] * sm->tile[(l + 1) * DC + dcol];
            a2 += sm->s_m[l + 2] * sm->tile[(l + 2) * DC + dcol];
            a3 += sm->s_m[l + 3] * sm->tile[(l + 3) * DC + dcol];
        }
        float mean = ((a0 + a1) + (a2 + a3)) * sm->s_minv;
        out_mean[(size_t)bs * EMB_D + (size_t)chunk * DC + dcol] = mean;
    }

    // Arg embeddings: sparse lists (avg ~5 entries each)
    for (int p = 0; p < NP; p++) {
        const int cnt = sm->s_cnt[p];           // uniform across block
        float acc = 0.f;
        for (int j = 0; j < cnt; j++) {
            int e = sm->s_list[p * L_TOK + j];  // broadcast read
            int l = e & 0xFF;
            float w = (float)(e >> 8);
            acc += w * sm->tile[l * DC + dcol];
        }
        float res = acc * sm->s_inv[p];
        int set = p >> 3;
        int a   = p & 7;
        float* dst = out_sets + (size_t)set * set_stride;
        dst[((size_t)bs * NARG + a) * EMB_D + (size_t)chunk * DC + dcol] = res;
    }
}

extern "C" void kernel_launch(void* const* d_in, const int* in_sizes, int n_in,
                              void* d_out, int out_size)
{
    const int*   sent = (const int*)  d_in[0];  // [B,S,L] int32
    const int*   mask = (const int*)  d_in[1];  // [B,S,L] int32
    const int*   pred = (const int*)  d_in[2];  // [B,S,A,T] int32
    const int*   a0   = (const int*)  d_in[3];
    const int*   a1   = (const int*)  d_in[4];
    const float* emb  = (const float*)d_in[5];  // [B,S,L,D] fp32
    float*       out  = (float*)      d_out;

    const int BS = in_sizes[0] / L_TOK;         // 256

    const size_t smem_bytes = sizeof(SmemLayout);
    cudaFuncSetAttribute(slmuse_fused_kernel,
                         cudaFuncAttributeMaxDynamicSharedMemorySize,
                         (int)smem_bytes);

    slmuse_fused_kernel<<<BS * NCHUNK, BDIM, smem_bytes>>>(
        sent, mask, pred, a0, a1, emb, out, BS);
}

// round 2
// speedup vs baseline: 1.7868x; 1.7868x over previous
#include <cuda_runtime.h>
#include <cuda_bf16.h>

// Problem constants (fixed by the reference: B=16,S=16 -> BS=256)
#define L_TOK   128          // tokens per sentence
#define NARG    8            // A
#define NTOK    8            // T
#define EMB_D   768          // D
#define DC      256          // D-chunk per CTA
#define NCHUNK  (EMB_D / DC) // 3
#define NP      24           // 3 arg-sets * NARG
#define BDIM    256

// Small shared memory: ids / mask / sparse match lists only (~14 KB).
struct SmemLayout {
    int   s_ids[L_TOK];          // sentence ids
    float s_m[L_TOK];            // attention mask (as float)
    int   s_arg[NP * NTOK];      // arg ids, [p][t]
    int   s_list[NP * L_TOK];    // packed (l | w<<8) nonzero entries per p
    int   s_cnt[NP];             // nonzero-entry count per p
    int   s_tot[NP];             // total matched-token count per p
    float s_inv[NP];             // 1/tot, or 0 if tot==0
    float s_minv;                // 1/max(sum(mask),1)
};

__global__ void __launch_bounds__(BDIM)
slmuse_fused_kernel(const int*   __restrict__ sent_ids,
                    const int*   __restrict__ att_mask,
                    const int*   __restrict__ pred_ids,
                    const int*   __restrict__ arg0_ids,
                    const int*   __restrict__ arg1_ids,
                    const float* __restrict__ emb,
                    float*       __restrict__ out,     // concatenated tuple
                    int BS)                            // B*S = 256
{
    __shared__ SmemLayout sm;

    const int tid   = threadIdx.x;
    const int bs    = blockIdx.x / NCHUNK;
    const int chunk = blockIdx.x % NCHUNK;

    float* out_mean = out;                                      // [BS, D]
    float* out_sets = out + (size_t)BS * EMB_D;                 // 3 x [BS, A, D]
    const size_t set_stride = (size_t)BS * NARG * EMB_D;

    // ---- Phase 1: load ids / mask / arg ids into smem ----
    if (tid < L_TOK) {
        sm.s_ids[tid] = sent_ids[(size_t)bs * L_TOK + tid];
        sm.s_m[tid]   = (float)att_mask[(size_t)bs * L_TOK + tid];
    }
    if (tid < NP * NTOK) {                 // 192 threads
        int p = tid / NTOK, t = tid % NTOK;
        int set = p / NARG, a = p % NARG;
        const int* src = (set == 0) ? pred_ids : (set == 1) ? arg0_ids : arg1_ids;
        sm.s_arg[tid] = src[((size_t)bs * NARG + a) * NTOK + t];
    }
    if (tid < NP) { sm.s_cnt[tid] = 0; sm.s_tot[tid] = 0; }
    __syncthreads();

    // ---- Phase 2: build compact nonzero weight lists (3072 tiny tasks) ----
    for (int task = tid; task < NP * L_TOK; task += BDIM) {
        int p = task >> 7;          // /128
        int l = task & (L_TOK - 1);
        int sid = sm.s_ids[l];
        int w = 0;
        #pragma unroll
        for (int t = 0; t < NTOK; t++) {
            int aid = sm.s_arg[p * NTOK + t];
            w += (aid != 0 && aid == sid) ? 1 : 0;
        }
        if (w) {
            int pos = atomicAdd(&sm.s_cnt[p], 1);
            sm.s_list[p * L_TOK + pos] = l | (w << 8);
            atomicAdd(&sm.s_tot[p], w);
        }
    }
    __syncthreads();

    if (tid == 0) {
        float ms = 0.f;
        #pragma unroll 8
        for (int l = 0; l < L_TOK; l++) ms += sm.s_m[l];
        sm.s_minv = 1.f / fmaxf(ms, 1.f);
    }
    if (tid < NP) {
        int tot = sm.s_tot[tid];
        sm.s_inv[tid] = (tot > 0) ? (1.f / (float)tot) : 0.f;  // 0 => where(counts>0,...,0)
    }
    __syncthreads();

    // ---- Phase 3: mean pool, streaming directly from global (coalesced). ----
    // Thread tid owns column (chunk*DC + tid). For fixed l, the warp reads
    // 128 contiguous bytes -> fully coalesced. Unroll-8 gives MLP=8/thread.
    const float* col_base = emb + (size_t)bs * L_TOK * EMB_D
                                + (size_t)chunk * DC + tid;
    {
        float a0 = 0.f, a1 = 0.f, a2 = 0.f, a3 = 0.f;
        float a4 = 0.f, a5 = 0.f, a6 = 0.f, a7 = 0.f;
        #pragma unroll 2
        for (int l = 0; l < L_TOK; l += 8) {
            float v0 = col_base[(size_t)(l + 0) * EMB_D];
            float v1 = col_base[(size_t)(l + 1) * EMB_D];
            float v2 = col_base[(size_t)(l + 2) * EMB_D];
            float v3 = col_base[(size_t)(l + 3) * EMB_D];
            float v4 = col_base[(size_t)(l + 4) * EMB_D];
            float v5 = col_base[(size_t)(l + 5) * EMB_D];
            float v6 = col_base[(size_t)(l + 6) * EMB_D];
            float v7 = col_base[(size_t)(l + 7) * EMB_D];
            a0 += sm.s_m[l + 0] * v0;
            a1 += sm.s_m[l + 1] * v1;
            a2 += sm.s_m[l + 2] * v2;
            a3 += sm.s_m[l + 3] * v3;
            a4 += sm.s_m[l + 4] * v4;
            a5 += sm.s_m[l + 5] * v5;
            a6 += sm.s_m[l + 6] * v6;
            a7 += sm.s_m[l + 7] * v7;
        }
        float mean = (((a0 + a1) + (a2 + a3)) + ((a4 + a5) + (a6 + a7))) * sm.s_minv;
        out_mean[(size_t)bs * EMB_D + (size_t)chunk * DC + tid] = mean;
    }

    // ---- Phase 4: sparse arg embeddings, re-reading rows from L1/L2. ----
    // Avg ~5 entries per p; rows were just streamed so they hit cache.
    for (int p = 0; p < NP; p++) {
        const int cnt = sm.s_cnt[p];           // uniform across block
        float acc0 = 0.f, acc1 = 0.f;
        int j = 0;
        for (; j + 2 <= cnt; j += 2) {         // 2-wide for load MLP
            int e0 = sm.s_list[p * L_TOK + j];
            int e1 = sm.s_list[p * L_TOK + j + 1];
            float v0 = col_base[(size_t)(e0 & 0xFF) * EMB_D];
            float v1 = col_base[(size_t)(e1 & 0xFF) * EMB_D];
            acc0 += (float)(e0 >> 8) * v0;
            acc1 += (float)(e1 >> 8) * v1;
        }
        if (j < cnt) {
            int e0 = sm.s_list[p * L_TOK + j];
            acc0 += (float)(e0 >> 8) * col_base[(size_t)(e0 & 0xFF) * EMB_D];
        }
        float res = (acc0 + acc1) * sm.s_inv[p];
        int set = p >> 3;
        int a   = p & 7;
        float* dst = out_sets + (size_t)set * set_stride;
        dst[((size_t)bs * NARG + a) * EMB_D + (size_t)chunk * DC + tid] = res;
    }
}

extern "C" void kernel_launch(void* const* d_in, const int* in_sizes, int n_in,
                              void* d_out, int out_size)
{
    const int*   sent = (const int*)  d_in[0];  // [B,S,L] int32
    const int*   mask = (const int*)  d_in[1];  // [B,S,L] int32
    const int*   pred = (const int*)  d_in[2];  // [B,S,A,T] int32
    const int*   a0   = (const int*)  d_in[3];
    const int*   a1   = (const int*)  d_in[4];
    const float* emb  = (const float*)d_in[5];  // [B,S,L,D] fp32
    float*       out  = (float*)      d_out;

    const int BS = in_sizes[0] / L_TOK;         // 256

    slmuse_fused_kernel<<<BS * NCHUNK, BDIM>>>(
        sent, mask, pred, a0, a1, emb, out, BS);
}